// round 1
// baseline (speedup 1.0000x reference)
#include <cuda_runtime.h>
#include <math.h>

// Problem constants (from metadata: x[32768,1024], W1[1024,1024], b1[1024], W2, b2)
#define DIM 1024
#define NMAX 32768

#define MAXNORM (1.0f - 1e-5f)   // (1 - EPS)/sqrt(c), c = 1
#define MIN_NORM 1e-15f

// ---------------------------------------------------------------------------
// Scratch (device globals: the sanctioned allocation-free workaround)
// ---------------------------------------------------------------------------
__device__ float g_mx[(size_t)NMAX * DIM];  // layer-1 intermediate (in-place h1)
__device__ float g_xn[NMAX];                // per-row input norms
__device__ float g_hb[2][DIM];              // hyperbolic biases per layer
__device__ float g_y2[2];                   // ||hyp_bias||^2 per layer

// ---------------------------------------------------------------------------
// Helpers
// ---------------------------------------------------------------------------
__device__ __forceinline__ float artanh_clip(float x) {
    // jnp.arctanh(jnp.clip(x, -1+1e-7, 1-1e-7))
    const float lim = 1.0f - 1e-7f;
    x = fminf(fmaxf(x, -lim), lim);
    return atanhf(x);
}

// Block-wide sum over 256 threads. All threads must participate.
__device__ __forceinline__ float blockReduceSum(float v) {
    __shared__ float sbuf[32];
    #pragma unroll
    for (int o = 16; o > 0; o >>= 1) v += __shfl_xor_sync(0xffffffffu, v, o);
    const int lane = threadIdx.x & 31;
    const int w    = threadIdx.x >> 5;
    if (lane == 0) sbuf[w] = v;
    __syncthreads();
    if (w == 0) {
        float t = (lane < 8) ? sbuf[lane] : 0.0f;
        #pragma unroll
        for (int o = 4; o > 0; o >>= 1) t += __shfl_xor_sync(0xffffffffu, t, o);
        if (lane == 0) sbuf[0] = t;
    }
    __syncthreads();
    float r = sbuf[0];
    __syncthreads();   // sbuf reusable after return
    return r;
}

// ---------------------------------------------------------------------------
// Per-row L2 norm (clamped): xn[r] = max(||X[r,:]||, 1e-15)
// one block per row, 256 threads, 4 elems each (float4)
// ---------------------------------------------------------------------------
__global__ __launch_bounds__(256)
void rownorm_kernel(const float* __restrict__ X, float* __restrict__ xn) {
    const float4 v = reinterpret_cast<const float4*>(X + (size_t)blockIdx.x * DIM)[threadIdx.x];
    float s = v.x * v.x + v.y * v.y + v.z * v.z + v.w * v.w;
    s = blockReduceSum(s);
    if (threadIdx.x == 0) xn[blockIdx.x] = fmaxf(sqrtf(s), MIN_NORM);
}

// ---------------------------------------------------------------------------
// hyp_bias = proj(expmap0(b)) ; also store ||hyp_bias||^2
// single block, 256 threads
// ---------------------------------------------------------------------------
__global__ __launch_bounds__(256)
void bias_kernel(const float* __restrict__ b, int layer) {
    const int t = threadIdx.x;
    float4 v = reinterpret_cast<const float4*>(b)[t];
    float w0 = v.x, w1 = v.y, w2 = v.z, w3 = v.w;

    // expmap0: n = max(||b||, 1e-15); e = tanh(n) * b / n
    float s = blockReduceSum(w0 * w0 + w1 * w1 + w2 * w2 + w3 * w3);
    float n = fmaxf(sqrtf(s), MIN_NORM);
    float sc = tanhf(n) / n;
    w0 *= sc; w1 *= sc; w2 *= sc; w3 *= sc;

    // proj
    float s2 = blockReduceSum(w0 * w0 + w1 * w1 + w2 * w2 + w3 * w3);
    float n2 = fmaxf(sqrtf(s2), MIN_NORM);
    if (n2 > MAXNORM) {
        float f = MAXNORM / n2;
        w0 *= f; w1 *= f; w2 *= f; w3 *= f;
    }

    // y2 on final values
    float s3 = blockReduceSum(w0 * w0 + w1 * w1 + w2 * w2 + w3 * w3);

    reinterpret_cast<float4*>(g_hb[layer])[t] = make_float4(w0, w1, w2, w3);
    if (t == 0) g_y2[layer] = s3;
}

// ---------------------------------------------------------------------------
// SGEMM (NT): C[n,m] = sum_k A[n,k] * B[m,k].  128x128x8 tiles, 256 threads,
// 8x8 per thread, double-buffered shared memory.
// ---------------------------------------------------------------------------
__global__ __launch_bounds__(256, 2)
void sgemm_nt_kernel(const float* __restrict__ A,
                     const float* __restrict__ B,
                     float* __restrict__ C,
                     int K, int ldc) {
    __shared__ float As[2][8][128];
    __shared__ float Bs[2][8][128];

    const int tid = threadIdx.x;
    const int m0  = blockIdx.y * 128;
    const int n0  = blockIdx.x * 128;

    const int lr = tid >> 1;          // 0..127 row within tile
    const int lk = (tid & 1) << 2;    // 0 or 4

    const float* Aptr = A + (size_t)(m0 + lr) * K + lk;
    const float* Bptr = B + (size_t)(n0 + lr) * K + lk;

    float4 ra = *reinterpret_cast<const float4*>(Aptr);
    float4 rb = *reinterpret_cast<const float4*>(Bptr);
    As[0][lk + 0][lr] = ra.x; As[0][lk + 1][lr] = ra.y;
    As[0][lk + 2][lr] = ra.z; As[0][lk + 3][lr] = ra.w;
    Bs[0][lk + 0][lr] = rb.x; Bs[0][lk + 1][lr] = rb.y;
    Bs[0][lk + 2][lr] = rb.z; Bs[0][lk + 3][lr] = rb.w;
    __syncthreads();

    const int tm = (tid >> 4) << 2;   // 0..60 step 4
    const int tn = (tid & 15) << 2;

    float acc[8][8];
    #pragma unroll
    for (int i = 0; i < 8; ++i)
        #pragma unroll
        for (int j = 0; j < 8; ++j) acc[i][j] = 0.0f;

    const int KT = K >> 3;
    int cur = 0;
    for (int kt = 0; kt < KT; ++kt) {
        if (kt + 1 < KT) {
            ra = *reinterpret_cast<const float4*>(Aptr + (size_t)(kt + 1) * 8);
            rb = *reinterpret_cast<const float4*>(Bptr + (size_t)(kt + 1) * 8);
        }
        #pragma unroll
        for (int k = 0; k < 8; ++k) {
            float a[8], b[8];
            *reinterpret_cast<float4*>(a)     = *reinterpret_cast<const float4*>(&As[cur][k][tm]);
            *reinterpret_cast<float4*>(a + 4) = *reinterpret_cast<const float4*>(&As[cur][k][tm + 64]);
            *reinterpret_cast<float4*>(b)     = *reinterpret_cast<const float4*>(&Bs[cur][k][tn]);
            *reinterpret_cast<float4*>(b + 4) = *reinterpret_cast<const float4*>(&Bs[cur][k][tn + 64]);
            #pragma unroll
            for (int i = 0; i < 8; ++i)
                #pragma unroll
                for (int j = 0; j < 8; ++j)
                    acc[i][j] = fmaf(a[i], b[j], acc[i][j]);
        }
        if (kt + 1 < KT) {
            const int nxt = cur ^ 1;
            As[nxt][lk + 0][lr] = ra.x; As[nxt][lk + 1][lr] = ra.y;
            As[nxt][lk + 2][lr] = ra.z; As[nxt][lk + 3][lr] = ra.w;
            Bs[nxt][lk + 0][lr] = rb.x; Bs[nxt][lk + 1][lr] = rb.y;
            Bs[nxt][lk + 2][lr] = rb.z; Bs[nxt][lk + 3][lr] = rb.w;
            __syncthreads();
            cur = nxt;
        }
    }

    #pragma unroll
    for (int i = 0; i < 8; ++i) {
        const int r = m0 + tm + ((i < 4) ? i : (60 + i));   // i>=4 -> tm+64+(i-4)
        float4 c0 = make_float4(acc[i][0], acc[i][1], acc[i][2], acc[i][3]);
        float4 c1 = make_float4(acc[i][4], acc[i][5], acc[i][6], acc[i][7]);
        *reinterpret_cast<float4*>(&C[(size_t)r * ldc + n0 + tn])      = c0;
        *reinterpret_cast<float4*>(&C[(size_t)r * ldc + n0 + tn + 64]) = c1;
    }
}

// ---------------------------------------------------------------------------
// Fused per-row epilogue: everything after the GEMM for one layer.
//   mx -> gyro_matvec scale -> proj -> gyro_add(bias) -> proj
//      -> proj -> logmap0 -> tanh -> expmap0 -> proj  (hyp_tanh_act)
// One block per row; row (1024 floats) is register-resident; in-place safe.
// ---------------------------------------------------------------------------
__global__ __launch_bounds__(256)
void rowpost_kernel(const float* __restrict__ MX,
                    const float* __restrict__ xnv,
                    float* __restrict__ OUT,
                    int layer) {
    const int t = threadIdx.x;
    const size_t base = (size_t)blockIdx.x * DIM;

    float4 v = reinterpret_cast<const float4*>(MX + base)[t];
    float w[4] = {v.x, v.y, v.z, v.w};

    // ---- gyro_matvec tail: res = tanh(mxn/xn * artanh(xn)) * mx / mxn ----
    float r1 = blockReduceSum(w[0]*w[0] + w[1]*w[1] + w[2]*w[2] + w[3]*w[3]);
    const bool allzero = (r1 == 0.0f);
    const float mxn = fmaxf(sqrtf(r1), MIN_NORM);
    const float xn  = xnv[blockIdx.x];
    const float arg = (mxn / xn) * artanh_clip(xn);
    float sres = tanhf(arg) / mxn;
    if (allzero) sres = 0.0f;
    #pragma unroll
    for (int i = 0; i < 4; ++i) w[i] *= sres;

    // ---- proj ----
    {
        float s = blockReduceSum(w[0]*w[0] + w[1]*w[1] + w[2]*w[2] + w[3]*w[3]);
        float n = fmaxf(sqrtf(s), MIN_NORM);
        if (n > MAXNORM) { float f = MAXNORM / n; w[0]*=f; w[1]*=f; w[2]*=f; w[3]*=f; }
    }

    // ---- gyro_add with hyp_bias ----
    float4 hv = reinterpret_cast<const float4*>(g_hb[layer])[t];
    float h[4] = {hv.x, hv.y, hv.z, hv.w};
    {
        float x2 = blockReduceSum(w[0]*w[0] + w[1]*w[1] + w[2]*w[2] + w[3]*w[3]);
        float xy = blockReduceSum(w[0]*h[0] + w[1]*h[1] + w[2]*h[2] + w[3]*h[3]);
        float y2 = g_y2[layer];
        float alpha = 1.0f + 2.0f * xy + y2;
        float beta  = 1.0f - x2;
        float den   = fmaxf(1.0f + 2.0f * xy + x2 * y2, MIN_NORM);
        float inv   = 1.0f / den;
        #pragma unroll
        for (int i = 0; i < 4; ++i) w[i] = (alpha * w[i] + beta * h[i]) * inv;
    }

    // ---- proj (end of hyp_linear) ----
    {
        float s = blockReduceSum(w[0]*w[0] + w[1]*w[1] + w[2]*w[2] + w[3]*w[3]);
        float n = fmaxf(sqrtf(s), MIN_NORM);
        if (n > MAXNORM) { float f = MAXNORM / n; w[0]*=f; w[1]*=f; w[2]*=f; w[3]*=f; }
    }

    // ---- hyp_tanh_act: proj -> logmap0 -> tanh -> expmap0 -> proj ----
    {
        float s = blockReduceSum(w[0]*w[0] + w[1]*w[1] + w[2]*w[2] + w[3]*w[3]);
        float n = fmaxf(sqrtf(s), MIN_NORM);
        if (n > MAXNORM) { float f = MAXNORM / n; w[0]*=f; w[1]*=f; w[2]*=f; w[3]*=f; }
    }
    {
        // logmap0: scale = artanh(n)/n  (recompute norm like the reference)
        float s = blockReduceSum(w[0]*w[0] + w[1]*w[1] + w[2]*w[2] + w[3]*w[3]);
        float n = fmaxf(sqrtf(s), MIN_NORM);
        float sl = artanh_clip(n) / n;
        #pragma unroll
        for (int i = 0; i < 4; ++i) w[i] = tanhf(sl * w[i]);
    }
    {
        // expmap0
        float s = blockReduceSum(w[0]*w[0] + w[1]*w[1] + w[2]*w[2] + w[3]*w[3]);
        float tn = fmaxf(sqrtf(s), MIN_NORM);
        float se = tanhf(tn) / tn;
        #pragma unroll
        for (int i = 0; i < 4; ++i) w[i] *= se;
    }
    {
        float s = blockReduceSum(w[0]*w[0] + w[1]*w[1] + w[2]*w[2] + w[3]*w[3]);
        float n = fmaxf(sqrtf(s), MIN_NORM);
        if (n > MAXNORM) { float f = MAXNORM / n; w[0]*=f; w[1]*=f; w[2]*=f; w[3]*=f; }
    }

    reinterpret_cast<float4*>(OUT + base)[t] = make_float4(w[0], w[1], w[2], w[3]);
}

// ---------------------------------------------------------------------------
// Launch
// ---------------------------------------------------------------------------
extern "C" void kernel_launch(void* const* d_in, const int* in_sizes, int n_in,
                              void* d_out, int out_size) {
    const float* x  = (const float*)d_in[0];
    const float* W1 = (const float*)d_in[1];
    const float* b1 = (const float*)d_in[2];
    const float* W2 = (const float*)d_in[3];
    const float* b2 = (const float*)d_in[4];
    float* out = (float*)d_out;

    const int N = in_sizes[0] / DIM;   // 32768

    float *mx = nullptr, *xn = nullptr;
    cudaGetSymbolAddress((void**)&mx, g_mx);
    cudaGetSymbolAddress((void**)&xn, g_xn);

    const dim3 ggrid(DIM / 128, N / 128);

    // biases (tiny; b==0 in this dataset but computed generally)
    bias_kernel<<<1, 256>>>(b1, 0);
    bias_kernel<<<1, 256>>>(b2, 1);

    // layer 1
    rownorm_kernel<<<N, 256>>>(x, xn);
    sgemm_nt_kernel<<<ggrid, 256>>>(x, W1, mx, DIM, DIM);
    rowpost_kernel<<<N, 256>>>(mx, xn, mx, 0);       // in-place: h1 lives in g_mx

    // layer 2
    rownorm_kernel<<<N, 256>>>(mx, xn);
    sgemm_nt_kernel<<<ggrid, 256>>>(mx, W2, out, DIM, DIM);
    rowpost_kernel<<<N, 256>>>(out, xn, out, 1);     // in-place into d_out
}

// round 3
// speedup vs baseline: 2.0618x; 2.0618x over previous
#include <cuda_runtime.h>
#include <cuda_bf16.h>
#include <math.h>
#include <stdint.h>

#define DIM 1024
#define NMAX 32768
#define MAXNORM (1.0f - 1e-5f)
#define MIN_NORM 1e-15f

// ---------------- GEMM tiling ----------------
#define BM 128
#define BN 128
#define BKE 32                     // bf16 k elements per stage (64 bytes per row)
#define KITERS (DIM / BKE)         // 32
#define STAGE_BYTES 32768          // Ah 8K + Al 8K + Bh 8K + Bl 8K
#define SMEM_BYTES (2 * STAGE_BYTES)

// ---------------- scratch (device globals) ----------------
__device__ float          g_mx[(size_t)NMAX * DIM];   // fp32 GEMM output
__device__ __nv_bfloat16  g_ah[(size_t)NMAX * DIM];   // activation hi split
__device__ __nv_bfloat16  g_al[(size_t)NMAX * DIM];   // activation lo split
__device__ __nv_bfloat16  g_w1h[DIM * DIM], g_w1l[DIM * DIM];
__device__ __nv_bfloat16  g_w2h[DIM * DIM], g_w2l[DIM * DIM];
__device__ float          g_xn[NMAX];
__device__ float          g_hb[2][DIM];
__device__ float          g_y2[2];

// ---------------- PTX helpers ----------------
__device__ __forceinline__ uint32_t smem_u32(const void* p) {
    uint32_t a;
    asm("{ .reg .u64 t; cvta.to.shared.u64 t, %1; cvt.u32.u64 %0, t; }" : "=r"(a) : "l"(p));
    return a;
}
#define CP_ASYNC16(dst, src) \
    asm volatile("cp.async.cg.shared.global [%0], [%1], 16;" :: "r"(dst), "l"(src) : "memory")
#define CP_COMMIT() asm volatile("cp.async.commit_group;" ::: "memory")
#define CP_WAIT1()  asm volatile("cp.async.wait_group 1;" ::: "memory")
#define CP_WAIT0()  asm volatile("cp.async.wait_group 0;" ::: "memory")

__device__ __forceinline__ void ldsm4(uint32_t* r, uint32_t addr) {
    asm volatile("ldmatrix.sync.aligned.m8n8.x4.shared.b16 {%0,%1,%2,%3}, [%4];"
                 : "=r"(r[0]), "=r"(r[1]), "=r"(r[2]), "=r"(r[3]) : "r"(addr));
}
__device__ __forceinline__ void mma16816(float* c, const uint32_t* a, uint32_t b0, uint32_t b1) {
    asm volatile("mma.sync.aligned.m16n8k16.row.col.f32.bf16.bf16.f32 "
                 "{%0,%1,%2,%3}, {%4,%5,%6,%7}, {%8,%9}, {%0,%1,%2,%3};"
                 : "+f"(c[0]), "+f"(c[1]), "+f"(c[2]), "+f"(c[3])
                 : "r"(a[0]), "r"(a[1]), "r"(a[2]), "r"(a[3]), "r"(b0), "r"(b1));
}

// ---------------- generic helpers ----------------
__device__ __forceinline__ float artanh_clip(float x) {
    const float lim = 1.0f - 1e-7f;
    x = fminf(fmaxf(x, -lim), lim);
    return atanhf(x);
}
__device__ __forceinline__ float blockReduceSum(float v) {
    __shared__ float sbuf[32];
    #pragma unroll
    for (int o = 16; o > 0; o >>= 1) v += __shfl_xor_sync(0xffffffffu, v, o);
    const int lane = threadIdx.x & 31;
    const int w    = threadIdx.x >> 5;
    if (lane == 0) sbuf[w] = v;
    __syncthreads();
    if (w == 0) {
        float t = (lane < 8) ? sbuf[lane] : 0.0f;
        #pragma unroll
        for (int o = 4; o > 0; o >>= 1) t += __shfl_xor_sync(0xffffffffu, t, o);
        if (lane == 0) sbuf[0] = t;
    }
    __syncthreads();
    float r = sbuf[0];
    __syncthreads();
    return r;
}
__device__ __forceinline__ void split1(float x, __nv_bfloat16& h, __nv_bfloat16& l) {
    h = __float2bfloat16(x);
    l = __float2bfloat16(x - __bfloat162float(h));
}

// ---------------- small kernels ----------------
__global__ __launch_bounds__(256)
void splitw_kernel(const float* __restrict__ W, __nv_bfloat16* __restrict__ H, __nv_bfloat16* __restrict__ L) {
    const size_t i = (size_t)blockIdx.x * 256 + threadIdx.x;
    float4 v = reinterpret_cast<const float4*>(W)[i];
    __nv_bfloat16 h[4], l[4];
    split1(v.x, h[0], l[0]); split1(v.y, h[1], l[1]);
    split1(v.z, h[2], l[2]); split1(v.w, h[3], l[3]);
    __nv_bfloat162 h01; h01.x = h[0]; h01.y = h[1];
    __nv_bfloat162 h23; h23.x = h[2]; h23.y = h[3];
    __nv_bfloat162 l01; l01.x = l[0]; l01.y = l[1];
    __nv_bfloat162 l23; l23.x = l[2]; l23.y = l[3];
    reinterpret_cast<__nv_bfloat162*>(H)[i * 2 + 0] = h01;
    reinterpret_cast<__nv_bfloat162*>(H)[i * 2 + 1] = h23;
    reinterpret_cast<__nv_bfloat162*>(L)[i * 2 + 0] = l01;
    reinterpret_cast<__nv_bfloat162*>(L)[i * 2 + 1] = l23;
}

__global__ __launch_bounds__(256)
void splitx_kernel(const float* __restrict__ X, __nv_bfloat16* __restrict__ H,
                   __nv_bfloat16* __restrict__ L, float* __restrict__ xn) {
    const int t = threadIdx.x;
    const size_t base = (size_t)blockIdx.x * DIM;
    float4 v = reinterpret_cast<const float4*>(X + base)[t];
    float s = blockReduceSum(v.x * v.x + v.y * v.y + v.z * v.z + v.w * v.w);
    if (t == 0) xn[blockIdx.x] = fmaxf(sqrtf(s), MIN_NORM);
    __nv_bfloat16 h[4], l[4];
    split1(v.x, h[0], l[0]); split1(v.y, h[1], l[1]);
    split1(v.z, h[2], l[2]); split1(v.w, h[3], l[3]);
    __nv_bfloat162 h01; h01.x = h[0]; h01.y = h[1];
    __nv_bfloat162 h23; h23.x = h[2]; h23.y = h[3];
    __nv_bfloat162 l01; l01.x = l[0]; l01.y = l[1];
    __nv_bfloat162 l23; l23.x = l[2]; l23.y = l[3];
    reinterpret_cast<__nv_bfloat162*>(H + base)[t * 2 + 0] = h01;
    reinterpret_cast<__nv_bfloat162*>(H + base)[t * 2 + 1] = h23;
    reinterpret_cast<__nv_bfloat162*>(L + base)[t * 2 + 0] = l01;
    reinterpret_cast<__nv_bfloat162*>(L + base)[t * 2 + 1] = l23;
}

__global__ __launch_bounds__(256)
void bias_kernel(const float* __restrict__ b, int layer) {
    const int t = threadIdx.x;
    float4 v = reinterpret_cast<const float4*>(b)[t];
    float w0 = v.x, w1 = v.y, w2 = v.z, w3 = v.w;
    float s = blockReduceSum(w0*w0 + w1*w1 + w2*w2 + w3*w3);
    float n = fmaxf(sqrtf(s), MIN_NORM);
    float sc = tanhf(n) / n;
    w0 *= sc; w1 *= sc; w2 *= sc; w3 *= sc;
    float s2 = blockReduceSum(w0*w0 + w1*w1 + w2*w2 + w3*w3);
    float n2 = fmaxf(sqrtf(s2), MIN_NORM);
    if (n2 > MAXNORM) { float f = MAXNORM / n2; w0*=f; w1*=f; w2*=f; w3*=f; }
    float s3 = blockReduceSum(w0*w0 + w1*w1 + w2*w2 + w3*w3);
    reinterpret_cast<float4*>(g_hb[layer])[t] = make_float4(w0, w1, w2, w3);
    if (t == 0) g_y2[layer] = s3;
}

// ---------------- HMMA bf16x3 GEMM: C[m,n] = sum_k A[m,k]*B[n,k] (fp32 accum) ----------------
// SMEM chunk layout per array: chunk(row, c) at row*64 + (c ^ ((row>>1)&3))*16  (row<128, c<4)
__global__ __launch_bounds__(256, 2)
void gemm3_kernel(const __nv_bfloat16* __restrict__ Ah, const __nv_bfloat16* __restrict__ Al,
                  const __nv_bfloat16* __restrict__ Bh, const __nv_bfloat16* __restrict__ Bl,
                  float* __restrict__ C) {
    extern __shared__ char smem[];
    const uint32_t s32 = smem_u32(smem);

    const int tid = threadIdx.x;
    const int wid = tid >> 5;
    const int lid = tid & 31;
    const int m0 = blockIdx.y * BM;
    const int n0 = blockIdx.x * BN;
    const int warpM = (wid & 3) * 32;
    const int warpN = (wid >> 2) * 64;

    // ---- loader mapping: thread handles chunks i and i+256 of each array ----
    const int row0 = tid >> 2;           // 0..63
    const int cc   = tid & 3;            // chunk in row
    const uint32_t off0 = (uint32_t)(row0 * 64 + ((cc ^ ((row0 >> 1) & 3)) * 16));
    const int row1 = row0 + 64;
    const uint32_t off1 = (uint32_t)(row1 * 64 + ((cc ^ ((row1 >> 1) & 3)) * 16));

    const __nv_bfloat16* aH0 = Ah + (size_t)(m0 + row0) * DIM + cc * 8;
    const __nv_bfloat16* aL0 = Al + (size_t)(m0 + row0) * DIM + cc * 8;
    const __nv_bfloat16* bH0 = Bh + (size_t)(n0 + row0) * DIM + cc * 8;
    const __nv_bfloat16* bL0 = Bl + (size_t)(n0 + row0) * DIM + cc * 8;
    const size_t rstep = (size_t)64 * DIM;

    // ---- ldmatrix lane offsets ----
    uint32_t ofsA[2][2], ofsB[4][2];
    {
        const int lrow = (lid & 7) + ((lid >> 3) & 1) * 8;
        const int lchk = lid >> 4;       // 0 or 1
        #pragma unroll
        for (int mf = 0; mf < 2; ++mf)
            #pragma unroll
            for (int ks = 0; ks < 2; ++ks) {
                int r = warpM + mf * 16 + lrow;
                int c = 2 * ks + lchk;
                ofsA[mf][ks] = (uint32_t)(r * 64 + ((c ^ ((r >> 1) & 3)) * 16));
            }
        #pragma unroll
        for (int p = 0; p < 4; ++p)
            #pragma unroll
            for (int ks = 0; ks < 2; ++ks) {
                int r = warpN + p * 16 + lrow;
                int c = 2 * ks + lchk;
                ofsB[p][ks] = (uint32_t)(r * 64 + ((c ^ ((r >> 1) & 3)) * 16));
            }
    }

    float acc[2][8][4];
    #pragma unroll
    for (int i = 0; i < 2; ++i)
        #pragma unroll
        for (int j = 0; j < 8; ++j)
            #pragma unroll
            for (int q = 0; q < 4; ++q) acc[i][j][q] = 0.0f;

    // ---- async-copy pipeline ----
    auto issue = [&](int kt) {
        const int buf = kt & 1;
        const uint32_t sb = s32 + buf * STAGE_BYTES;
        const size_t ko = (size_t)kt * BKE;
        CP_ASYNC16(sb + off0,          aH0 + ko);
        CP_ASYNC16(sb + off1,          aH0 + rstep + ko);
        CP_ASYNC16(sb + 8192  + off0,  aL0 + ko);
        CP_ASYNC16(sb + 8192  + off1,  aL0 + rstep + ko);
        CP_ASYNC16(sb + 16384 + off0,  bH0 + ko);
        CP_ASYNC16(sb + 16384 + off1,  bH0 + rstep + ko);
        CP_ASYNC16(sb + 24576 + off0,  bL0 + ko);
        CP_ASYNC16(sb + 24576 + off1,  bL0 + rstep + ko);
    };

    issue(0); CP_COMMIT();
    for (int kt = 0; kt < KITERS; ++kt) {
        if (kt + 1 < KITERS) { issue(kt + 1); CP_COMMIT(); CP_WAIT1(); }
        else                 { CP_WAIT0(); }
        __syncthreads();

        const uint32_t sA = s32 + (kt & 1) * STAGE_BYTES;
        const uint32_t sB = sA + 16384;
        #pragma unroll
        for (int ks = 0; ks < 2; ++ks) {
            uint32_t ahf[2][4], alf[2][4];
            ldsm4(ahf[0], sA + ofsA[0][ks]);
            ldsm4(ahf[1], sA + ofsA[1][ks]);
            ldsm4(alf[0], sA + 8192 + ofsA[0][ks]);
            ldsm4(alf[1], sA + 8192 + ofsA[1][ks]);
            #pragma unroll
            for (int p = 0; p < 4; ++p) {
                uint32_t bh[4], bl[4];
                ldsm4(bh, sB + ofsB[p][ks]);
                ldsm4(bl, sB + 8192 + ofsB[p][ks]);
                #pragma unroll
                for (int mf = 0; mf < 2; ++mf) {
                    mma16816(acc[mf][2*p],   ahf[mf], bh[0], bh[2]);
                    mma16816(acc[mf][2*p],   ahf[mf], bl[0], bl[2]);
                    mma16816(acc[mf][2*p],   alf[mf], bh[0], bh[2]);
                    mma16816(acc[mf][2*p+1], ahf[mf], bh[1], bh[3]);
                    mma16816(acc[mf][2*p+1], ahf[mf], bl[1], bl[3]);
                    mma16816(acc[mf][2*p+1], alf[mf], bh[1], bh[3]);
                }
            }
        }
        __syncthreads();
    }

    // ---- epilogue: direct stores ----
    #pragma unroll
    for (int mf = 0; mf < 2; ++mf) {
        #pragma unroll
        for (int nf = 0; nf < 8; ++nf) {
            const int r   = m0 + warpM + mf * 16 + (lid >> 2);
            const int col = n0 + warpN + nf * 8 + (lid & 3) * 2;
            float2 v0 = make_float2(acc[mf][nf][0], acc[mf][nf][1]);
            float2 v1 = make_float2(acc[mf][nf][2], acc[mf][nf][3]);
            *reinterpret_cast<float2*>(&C[(size_t)r * DIM + col])       = v0;
            *reinterpret_cast<float2*>(&C[(size_t)(r + 8) * DIM + col]) = v1;
        }
    }
}

// ---------------- fused per-row epilogue ----------------
template<bool SPLIT>
__global__ __launch_bounds__(256)
void rowpost_kernel(const float* __restrict__ MX, const float* __restrict__ xnv,
                    float* __restrict__ OUT,
                    __nv_bfloat16* __restrict__ OH, __nv_bfloat16* __restrict__ OL,
                    float* __restrict__ xnout, int layer) {
    const int t = threadIdx.x;
    const size_t base = (size_t)blockIdx.x * DIM;

    float4 v = reinterpret_cast<const float4*>(MX + base)[t];
    float w[4] = {v.x, v.y, v.z, v.w};
    const float xn = xnv[blockIdx.x];

    // gyro_matvec tail
    float r1 = blockReduceSum(w[0]*w[0] + w[1]*w[1] + w[2]*w[2] + w[3]*w[3]);
    const bool allzero = (r1 == 0.0f);
    const float mxn = fmaxf(sqrtf(r1), MIN_NORM);
    const float arg = (mxn / xn) * artanh_clip(xn);
    float sres = tanhf(arg) / mxn;
    if (allzero) sres = 0.0f;
    #pragma unroll
    for (int i = 0; i < 4; ++i) w[i] *= sres;

    // proj
    {
        float s = blockReduceSum(w[0]*w[0] + w[1]*w[1] + w[2]*w[2] + w[3]*w[3]);
        float n = fmaxf(sqrtf(s), MIN_NORM);
        if (n > MAXNORM) { float f = MAXNORM / n; w[0]*=f; w[1]*=f; w[2]*=f; w[3]*=f; }
    }
    // gyro_add(hyp_bias)
    {
        float4 hv = reinterpret_cast<const float4*>(g_hb[layer])[t];
        float h[4] = {hv.x, hv.y, hv.z, hv.w};
        float x2 = blockReduceSum(w[0]*w[0] + w[1]*w[1] + w[2]*w[2] + w[3]*w[3]);
        float xy = blockReduceSum(w[0]*h[0] + w[1]*h[1] + w[2]*h[2] + w[3]*h[3]);
        float y2 = g_y2[layer];
        float alpha = 1.0f + 2.0f * xy + y2;
        float beta  = 1.0f - x2;
        float inv   = 1.0f / fmaxf(1.0f + 2.0f * xy + x2 * y2, MIN_NORM);
        #pragma unroll
        for (int i = 0; i < 4; ++i) w[i] = (alpha * w[i] + beta * h[i]) * inv;
    }
    // proj (end of hyp_linear)
    {
        float s = blockReduceSum(w[0]*w[0] + w[1]*w[1] + w[2]*w[2] + w[3]*w[3]);
        float n = fmaxf(sqrtf(s), MIN_NORM);
        if (n > MAXNORM) { float f = MAXNORM / n; w[0]*=f; w[1]*=f; w[2]*=f; w[3]*=f; }
    }
    // hyp_tanh_act: proj
    {
        float s = blockReduceSum(w[0]*w[0] + w[1]*w[1] + w[2]*w[2] + w[3]*w[3]);
        float n = fmaxf(sqrtf(s), MIN_NORM);
        if (n > MAXNORM) { float f = MAXNORM / n; w[0]*=f; w[1]*=f; w[2]*=f; w[3]*=f; }
    }
    // logmap0 + tanh
    {
        float s = blockReduceSum(w[0]*w[0] + w[1]*w[1] + w[2]*w[2] + w[3]*w[3]);
        float n = fmaxf(sqrtf(s), MIN_NORM);
        float sl = artanh_clip(n) / n;
        #pragma unroll
        for (int i = 0; i < 4; ++i) w[i] = tanhf(sl * w[i]);
    }
    // expmap0
    {
        float s = blockReduceSum(w[0]*w[0] + w[1]*w[1] + w[2]*w[2] + w[3]*w[3]);
        float tn = fmaxf(sqrtf(s), MIN_NORM);
        float se = tanhf(tn) / tn;
        #pragma unroll
        for (int i = 0; i < 4; ++i) w[i] *= se;
    }
    // final proj (+ next-layer norm)
    float nfin;
    {
        float s = blockReduceSum(w[0]*w[0] + w[1]*w[1] + w[2]*w[2] + w[3]*w[3]);
        float n = fmaxf(sqrtf(s), MIN_NORM);
        nfin = fminf(n, MAXNORM);
        if (n > MAXNORM) { float f = MAXNORM / n; w[0]*=f; w[1]*=f; w[2]*=f; w[3]*=f; }
    }

    if (SPLIT) {
        __nv_bfloat16 h[4], l[4];
        #pragma unroll
        for (int i = 0; i < 4; ++i) split1(w[i], h[i], l[i]);
        __nv_bfloat162 h01; h01.x = h[0]; h01.y = h[1];
        __nv_bfloat162 h23; h23.x = h[2]; h23.y = h[3];
        __nv_bfloat162 l01; l01.x = l[0]; l01.y = l[1];
        __nv_bfloat162 l23; l23.x = l[2]; l23.y = l[3];
        reinterpret_cast<__nv_bfloat162*>(OH + base)[t * 2 + 0] = h01;
        reinterpret_cast<__nv_bfloat162*>(OH + base)[t * 2 + 1] = h23;
        reinterpret_cast<__nv_bfloat162*>(OL + base)[t * 2 + 0] = l01;
        reinterpret_cast<__nv_bfloat162*>(OL + base)[t * 2 + 1] = l23;
        if (t == 0) xnout[blockIdx.x] = fmaxf(nfin, MIN_NORM);
    } else {
        reinterpret_cast<float4*>(OUT + base)[t] = make_float4(w[0], w[1], w[2], w[3]);
    }
}

// ---------------- launch ----------------
extern "C" void kernel_launch(void* const* d_in, const int* in_sizes, int n_in,
                              void* d_out, int out_size) {
    const float* x  = (const float*)d_in[0];
    const float* W1 = (const float*)d_in[1];
    const float* b1 = (const float*)d_in[2];
    const float* W2 = (const float*)d_in[3];
    const float* b2 = (const float*)d_in[4];
    float* out = (float*)d_out;

    const int N = in_sizes[0] / DIM;

    float *mx = nullptr, *xn = nullptr;
    __nv_bfloat16 *ah, *al, *w1h, *w1l, *w2h, *w2l;
    cudaGetSymbolAddress((void**)&mx,  g_mx);
    cudaGetSymbolAddress((void**)&xn,  g_xn);
    cudaGetSymbolAddress((void**)&ah,  g_ah);
    cudaGetSymbolAddress((void**)&al,  g_al);
    cudaGetSymbolAddress((void**)&w1h, g_w1h);
    cudaGetSymbolAddress((void**)&w1l, g_w1l);
    cudaGetSymbolAddress((void**)&w2h, g_w2h);
    cudaGetSymbolAddress((void**)&w2l, g_w2l);

    cudaFuncSetAttribute(gemm3_kernel, cudaFuncAttributeMaxDynamicSharedMemorySize, SMEM_BYTES);

    const dim3 ggrid(DIM / BN, N / BM);
    const int wgrid = (DIM * DIM) / (4 * 256);

    splitw_kernel<<<wgrid, 256>>>(W1, w1h, w1l);
    splitw_kernel<<<wgrid, 256>>>(W2, w2h, w2l);
    bias_kernel<<<1, 256>>>(b1, 0);
    bias_kernel<<<1, 256>>>(b2, 1);

    // layer 1
    splitx_kernel<<<N, 256>>>(x, ah, al, xn);
    gemm3_kernel<<<ggrid, 256, SMEM_BYTES>>>(ah, al, w1h, w1l, mx);
    rowpost_kernel<true><<<N, 256>>>(mx, xn, nullptr, ah, al, xn, 0);

    // layer 2
    gemm3_kernel<<<ggrid, 256, SMEM_BYTES>>>(ah, al, w2h, w2l, out);
    rowpost_kernel<false><<<N, 256>>>(out, xn, out, nullptr, nullptr, nullptr, 1);
}